// round 4
// baseline (speedup 1.0000x reference)
#include <cuda_runtime.h>
#include <math.h>

#define HH 512
#define WW 512
#define CHW 128
#define FHW 256
#define CF 256
#define NCc 3
#define NPTS 2048
#define NUM_OVER 6144
#define STEP1 1536
#define STEP2 512
#define BB 2
#define FEAT_DIM 259
#define FEAT_PAD 260                        // padded to 65*4 for float4
#define NCB1 65                             // 260/4 chunks, layer1+layer2
#define NROWS (BB*NPTS)                     // 4096
#define FINE_FLAT (BB*NPTS*CF)              // 1048576
#define FLAT_TOTAL (FINE_FLAT + BB*NPTS*NCc)
#define OUT_OFF (BB*NCc*NPTS)               // 12288
#define MASK_SIZE (BB*HH*WW)                // 524288
#define RPB 16                              // rows per block in MLP
#define SORT_N 8192                         // padded candidate count
#define NWORDS (HH*WW/32)                   // 8192 bitmap words
#define W1P_ELEMS (NCB1*256*4)              // 66560
#define W2P_ELEMS (NCB1*128*4)              // 33280
#define PREP_SEL_BLOCKS 2
#define PREP_REPACK_BLOCKS 98               // ceil((66560+33280)/1024)

// ---------------- device scratch (no allocations allowed) ----------------
__device__ int   g_pts[BB*NPTS];
__device__ float g_flat[FLAT_TOTAL];
__device__ float g_w1p[W1P_ELEMS];          // [cb][o][q]  (q = c%4)
__device__ float g_w2p[W2P_ELEMS];          // [cb][o][q]

// =========================================================================
// k_prep: blocks 0..1  -> per-batch point selection + sort + mask scatter
//         blocks 2..   -> weight repack for vectorized MLP
// Selection semantics identical to the passing R2 kernel:
//   top-STEP1 by uncertainty (desc), ties by candidate index (asc),
//   union with the STEP2 coverage tail, emitted in ascending linear order.
// =========================================================================
__global__ __launch_bounds__(1024) void k_prep(const float* __restrict__ coarse,
                                               const int* __restrict__ rnd,
                                               const float* __restrict__ w1,
                                               const float* __restrict__ w2,
                                               float* __restrict__ mask_out) {
    extern __shared__ unsigned long long keys[];   // 64KB; reused as bitmap
    __shared__ int pts_lin[NPTS];                  // 8KB
    __shared__ int warp_tot[32];

    if (blockIdx.x >= PREP_SEL_BLOCKS) {
        // ---- weight repack: w1p[cb][o][q] = w1[o][cb*4+q] (zero pad) ----
        int t = (blockIdx.x - PREP_SEL_BLOCKS) * 1024 + threadIdx.x;
        if (t < W1P_ELEMS) {
            int cb = t >> 10;              // / (256*4)
            int rest = t & 1023;
            int o = rest >> 2, q = rest & 3;
            int c = cb * 4 + q;
            g_w1p[t] = (c < FEAT_DIM) ? w1[o*FEAT_DIM + c] : 0.f;
        } else {
            int t2 = t - W1P_ELEMS;
            if (t2 < W2P_ELEMS) {
                int cb = t2 >> 9;          // / (128*4)
                int rest = t2 & 511;
                int o = rest >> 2, q = rest & 3;
                int c = cb * 4 + q;
                g_w2p[t2] = (c < FEAT_DIM) ? w2[o*FEAT_DIM + c] : 0.f;
            }
        }
        return;
    }

    int b = blockIdx.x;
    // ---- 1. uncertainty keys (bit-identical arithmetic to R2 k_unc) ----
    for (int j = threadIdx.x; j < NUM_OVER; j += 1024) {
        int idx = rnd[j];
        int h = idx / WW, w = idx % WW;
        float yc = (float)h * 0.25f - 0.375f;
        float xc = (float)w * 0.25f - 0.375f;
        int y0 = (int)floorf(yc); float fy = yc - (float)y0;
        int x0 = (int)floorf(xc); float fx = xc - (float)x0;
        int y0c = min(max(y0,   0), CHW-1), y1c = min(max(y0+1, 0), CHW-1);
        int x0c = min(max(x0,   0), CHW-1), x1c = min(max(x0+1, 0), CHW-1);
        float p[3];
        const float* base = coarse + (size_t)b * NCc * CHW * CHW;
#pragma unroll
        for (int c = 0; c < 3; c++) {
            const float* pc = base + c * CHW * CHW;
            float v00 = pc[y0c*CHW + x0c], v01 = pc[y0c*CHW + x1c];
            float v10 = pc[y1c*CHW + x0c], v11 = pc[y1c*CHW + x1c];
            float top = v00 * (1.f - fx) + v01 * fx;
            float bot = v10 * (1.f - fx) + v11 * fx;
            p[c] = top * (1.f - fy) + bot * fy;
        }
        float m  = fmaxf(p[0], fmaxf(p[1], p[2]));
        float e0 = expf(p[0]-m), e1 = expf(p[1]-m), e2 = expf(p[2]-m);
        float s  = e0 + e1 + e2;
        float q0 = e0/s, q1 = e1/s, q2 = e2/s;
        float mx  = fmaxf(q0, fmaxf(q1, q2));
        float mn  = fminf(q0, fminf(q1, q2));
        float mid = q0 + q1 + q2 - mx - mn;
        float u = 1.0f - (mx - mid);
        unsigned int bits = __float_as_uint(u);
        unsigned int okey = bits ^ ((bits >> 31) ? 0xFFFFFFFFu : 0x80000000u);
        // ascending sort of (~okey, j)  ==  u desc, index asc
        keys[j] = ((unsigned long long)(~okey) << 32) | (unsigned int)j;
    }
    for (int j = NUM_OVER + threadIdx.x; j < SORT_N; j += 1024)
        keys[j] = ~0ull;                       // pad sorts to the back
    __syncthreads();

    // ---- 2. bitonic sort, 8192 x 64-bit, ascending ----
    for (int k = 2; k <= SORT_N; k <<= 1) {
        for (int j = k >> 1; j > 0; j >>= 1) {
            for (int i = threadIdx.x; i < SORT_N; i += 1024) {
                int ixj = i ^ j;
                if (ixj > i) {
                    unsigned long long a = keys[i], c2 = keys[ixj];
                    bool up = ((i & k) == 0);
                    if ((a > c2) == up) { keys[i] = c2; keys[ixj] = a; }
                }
            }
            __syncthreads();
        }
    }

    // ---- 3. gather selected + coverage linear indices ----
    for (int t = threadIdx.x; t < STEP1; t += 1024) {
        int j = (int)(unsigned int)keys[t];    // low word = candidate index
        pts_lin[t] = rnd[j];
    }
    for (int t = threadIdx.x; t < STEP2; t += 1024)
        pts_lin[STEP1 + t] = rnd[HH*WW - STEP2 + t];
    __syncthreads();

    // ---- 4. bitmap (reuse keys memory) ----
    unsigned int* bitmap = (unsigned int*)keys;
    for (int w = threadIdx.x; w < NWORDS; w += 1024) bitmap[w] = 0u;
    __syncthreads();
    for (int t = threadIdx.x; t < NPTS; t += 1024) {
        int lin = pts_lin[t];
        atomicOr(&bitmap[lin >> 5], 1u << (lin & 31));
    }
    __syncthreads();

    // ---- 5. popcount scan + ordered emit ----
    int w0 = threadIdx.x * 8;
    unsigned int words[8];
    int cnt = 0;
#pragma unroll
    for (int q = 0; q < 8; q++) { words[q] = bitmap[w0 + q]; cnt += __popc(words[q]); }
    int lane = threadIdx.x & 31, wid = threadIdx.x >> 5;
    int incl = cnt;
#pragma unroll
    for (int o = 1; o < 32; o <<= 1) {
        int v = __shfl_up_sync(0xFFFFFFFFu, incl, o);
        if (lane >= o) incl += v;
    }
    if (lane == 31) warp_tot[wid] = incl;
    __syncthreads();
    int base = 0;
    for (int ww = 0; ww < 32; ww++) if (ww < wid) base += warp_tot[ww];
    int offset = base + incl - cnt;            // exclusive prefix
#pragma unroll
    for (int q = 0; q < 8; q++) {
        unsigned int m = words[q];
        int linbase = (w0 + q) * 32;
        while (m) {
            int bpos = __ffs(m) - 1; m &= m - 1;
            int lin = linbase + bpos;
            g_pts[b*NPTS + offset] = lin;
            mask_out[b*HH*WW + lin] = 1.0f;
            offset++;
        }
    }
}

// =========================================================================
// k_sample: gather fine (256ch, x2 bilinear) + coarse logits per point.
// Warp-uniform float2 fast path when x-taps are an aligned adjacent pair.
// =========================================================================
__global__ void k_sample(const float* __restrict__ fine, const float* __restrict__ coarse) {
    __shared__ int   sy0, sy1, sx0, sx1, cy0, cy1, cx0, cx1, sfast;
    __shared__ float sfy, sfx, cfy, cfx;
    int g = blockIdx.x;               // b*2048 + n (sorted order)
    int b = g >> 11;
    if (threadIdx.x == 0) {
        int idx = g_pts[g];
        int h = idx / WW, w = idx % WW;
        // fine: 256 -> 512, src = i/2 - 0.25
        float yf = (float)h * 0.5f - 0.25f;
        float xf = (float)w * 0.5f - 0.25f;
        int y0 = (int)floorf(yf); sfy = yf - (float)y0;
        int x0 = (int)floorf(xf); sfx = xf - (float)x0;
        sy0 = min(max(y0,   0), FHW-1); sy1 = min(max(y0+1, 0), FHW-1);
        sx0 = min(max(x0,   0), FHW-1); sx1 = min(max(x0+1, 0), FHW-1);
        sfast = (sx1 == sx0 + 1) && ((sx0 & 1) == 0);
        // coarse: 128 -> 512, src = i/4 - 0.375
        float yc = (float)h * 0.25f - 0.375f;
        float xc = (float)w * 0.25f - 0.375f;
        int cy = (int)floorf(yc); cfy = yc - (float)cy;
        int cx = (int)floorf(xc); cfx = xc - (float)cx;
        cy0 = min(max(cy,   0), CHW-1); cy1 = min(max(cy+1, 0), CHW-1);
        cx0 = min(max(cx,   0), CHW-1); cx1 = min(max(cx+1, 0), CHW-1);
    }
    __syncthreads();
    int c = threadIdx.x;              // 256 channels
    {
        const float* pf = fine + ((size_t)b * CF + c) * (FHW * FHW);
        float v00, v01, v10, v11;
        if (sfast) {                  // warp-uniform branch
            float2 a = *(const float2*)(pf + sy0*FHW + sx0);
            float2 d = *(const float2*)(pf + sy1*FHW + sx0);
            v00 = a.x; v01 = a.y; v10 = d.x; v11 = d.y;
        } else {
            v00 = pf[sy0*FHW + sx0]; v01 = pf[sy0*FHW + sx1];
            v10 = pf[sy1*FHW + sx0]; v11 = pf[sy1*FHW + sx1];
        }
        float top = v00 * (1.f - sfx) + v01 * sfx;
        float bot = v10 * (1.f - sfx) + v11 * sfx;
        g_flat[(size_t)g * CF + c] = top * (1.f - sfy) + bot * sfy;
    }
    if (c < NCc) {
        const float* pc = coarse + ((size_t)b * NCc + c) * (CHW * CHW);
        float v00 = pc[cy0*CHW + cx0], v01 = pc[cy0*CHW + cx1];
        float v10 = pc[cy1*CHW + cx0], v11 = pc[cy1*CHW + cx1];
        float top = v00 * (1.f - cfx) + v01 * cfx;
        float bot = v10 * (1.f - cfx) + v11 * cfx;
        g_flat[FINE_FLAT + (size_t)g * NCc + c] = top * (1.f - cfy) + bot * cfy;
    }
}

// =========================================================================
// k_mlp: 16 rows/block, channel loop vectorized x4 (LDG.128 weights,
// LDS.128 broadcast features) -> FMA-pipe bound.
// Rows read the SCRAMBLED flat buffer at g*259 exactly like the reference
// reshape (fine.ravel() ++ coarse.ravel() -> (B, NPTS, 259)).
// =========================================================================
__global__ __launch_bounds__(256) void k_mlp(const float* __restrict__ w3,
                                             const float* __restrict__ pa,
                                             float* __restrict__ out) {
    __shared__ __align__(16) float xs[RPB][FEAT_PAD];
    __shared__ __align__(16) float l1s[RPB][FEAT_PAD];
    __shared__ __align__(16) float l2s[RPB][128];
    int g0 = blockIdx.x * RPB;
    float a = *pa;
    for (int t = threadIdx.x; t < RPB*FEAT_DIM; t += 256) {
        int r = t / FEAT_DIM, c = t % FEAT_DIM;
        float v = g_flat[(size_t)(g0 + r) * FEAT_DIM + c];
        xs[r][c] = v;
        if (c >= 256) l1s[r][c] = v;          // tail feeds layer 2 directly
    }
    if (threadIdx.x < RPB) {                  // pad column 259 with zeros
        xs[threadIdx.x][259] = 0.f;
        l1s[threadIdx.x][259] = 0.f;
    }
    __syncthreads();
    // ---- layer 1: 259 -> 256, prelu ----
    int o = threadIdx.x;
    float acc[RPB];
#pragma unroll
    for (int r = 0; r < RPB; r++) acc[r] = 0.f;
    const float4* w1p4 = (const float4*)g_w1p;
    for (int cb = 0; cb < NCB1; cb++) {
        float4 wv = w1p4[cb*256 + o];
#pragma unroll
        for (int r = 0; r < RPB; r++) {
            float4 x4 = *(const float4*)&xs[r][cb*4];
            acc[r] = fmaf(wv.x, x4.x, acc[r]);
            acc[r] = fmaf(wv.y, x4.y, acc[r]);
            acc[r] = fmaf(wv.z, x4.z, acc[r]);
            acc[r] = fmaf(wv.w, x4.w, acc[r]);
        }
    }
#pragma unroll
    for (int r = 0; r < RPB; r++) l1s[r][o] = acc[r] >= 0.f ? acc[r] : a * acc[r];
    __syncthreads();
    // ---- layer 2: [l1(256) ++ tail(3)] -> 128, prelu ----
    {
        int o2 = threadIdx.x & 127;
        int r0 = threadIdx.x >> 7;            // 0 or 1; rows r0, r0+2, ...
        float acc2[RPB/2];
#pragma unroll
        for (int rr = 0; rr < RPB/2; rr++) acc2[rr] = 0.f;
        const float4* w2p4 = (const float4*)g_w2p;
        for (int cb = 0; cb < NCB1; cb++) {
            float4 wv = w2p4[cb*128 + o2];
#pragma unroll
            for (int rr = 0; rr < RPB/2; rr++) {
                float4 x4 = *(const float4*)&l1s[r0 + 2*rr][cb*4];
                acc2[rr] = fmaf(wv.x, x4.x, acc2[rr]);
                acc2[rr] = fmaf(wv.y, x4.y, acc2[rr]);
                acc2[rr] = fmaf(wv.z, x4.z, acc2[rr]);
                acc2[rr] = fmaf(wv.w, x4.w, acc2[rr]);
            }
        }
#pragma unroll
        for (int rr = 0; rr < RPB/2; rr++) {
            float v = acc2[rr];
            l2s[r0 + 2*rr][o2] = v >= 0.f ? v : a * v;
        }
    }
    __syncthreads();
    // ---- layer 3: [l2(128) ++ tail(3)] -> 3 ----
    if (threadIdx.x < RPB*NCc) {
        int r = threadIdx.x / 3, oo = threadIdx.x % 3;
        float s = 0.f;
        for (int c = 0; c < 128; c++) s = fmaf(w3[oo*131 + c], l2s[r][c], s);
#pragma unroll
        for (int t = 0; t < 3; t++)  s = fmaf(w3[oo*131 + 128 + t], xs[r][256 + t], s);
        int g = g0 + r;
        int b = g >> 11, n = g & 2047;
        out[(b*NCc + oo)*NPTS + n] = s;
    }
}

// ---------------- launch ----------------
extern "C" void kernel_launch(void* const* d_in, const int* in_sizes, int n_in,
                              void* d_out, int out_size) {
    const float* fine   = (const float*)d_in[0];   // (2,256,256,256)
    const float* coarse = (const float*)d_in[1];   // (2,3,128,128)
    const float* w1     = (const float*)d_in[2];   // (256,259)
    const float* w2     = (const float*)d_in[3];   // (128,259)
    const float* w3     = (const float*)d_in[4];   // (3,131)
    const float* pa     = (const float*)d_in[5];   // scalar
    const int*   rnd    = (const int*)d_in[6];     // (262144,)
    float* out = (float*)d_out;

    cudaFuncSetAttribute(k_prep, cudaFuncAttributeMaxDynamicSharedMemorySize,
                         SORT_N * (int)sizeof(unsigned long long));

    cudaMemsetAsync(out + OUT_OFF, 0, (size_t)MASK_SIZE * sizeof(float), 0);
    k_prep<<<PREP_SEL_BLOCKS + PREP_REPACK_BLOCKS, 1024,
             SORT_N * sizeof(unsigned long long)>>>(coarse, rnd, w1, w2, out + OUT_OFF);
    k_sample<<<NROWS, 256>>>(fine, coarse);
    k_mlp<<<NROWS/RPB, 256>>>(w3, pa, out);
    (void)in_sizes; (void)n_in; (void)out_size;
}

// round 5
// speedup vs baseline: 1.3691x; 1.3691x over previous
#include <cuda_runtime.h>
#include <math.h>

#define HH 512
#define WW 512
#define CHW 128
#define FHW 256
#define CF 256
#define NCc 3
#define NPTS 2048
#define NUM_OVER 6144
#define STEP1 1536
#define STEP2 512
#define BB 2
#define FEAT_DIM 259
#define FEAT_PAD 260                        // padded to 65*4 for float4
#define NCB1 65                             // 260/4 chunks, layer1+layer2
#define NROWS (BB*NPTS)                     // 4096
#define FINE_FLAT (BB*NPTS*CF)              // 1048576
#define FLAT_TOTAL (FINE_FLAT + BB*NPTS*NCc)
#define OUT_OFF (BB*NCc*NPTS)               // 12288
#define MASK_SIZE (BB*HH*WW)                // 524288
#define RPB 16                              // rows per block in MLP
#define NWORDS (HH*WW/32)                   // 8192 bitmap words (32KB)
#define SELW (NUM_OVER/32)                  // 192 selection-flag words
#define W1P_ELEMS (NCB1*256*4)              // 66560
#define W2P_ELEMS (NCB1*128*4)              // 33280
#define PREP_SEL_BLOCKS 2
#define PREP_REPACK_BLOCKS 98               // ceil((66560+33280)/1024)

// ---------------- device scratch (no allocations allowed) ----------------
__device__ int   g_pts[BB*NPTS];
__device__ float g_flat[FLAT_TOTAL];
__device__ float g_w1p[W1P_ELEMS];          // [cb][o][q]  (q = c%4)
__device__ float g_w2p[W2P_ELEMS];          // [cb][o][q]

// =========================================================================
// k_prep: blocks 0..1  -> per-batch selection via RADIX THRESHOLD (no sort)
//         blocks 2..   -> weight repack for vectorized MLP
// Selection semantics identical to the R2/R3 passing kernels:
//   top-STEP1 by uncertainty (desc), ties by candidate index (asc),
//   union with the STEP2 coverage tail, emitted in ascending linear order.
// =========================================================================
__global__ __launch_bounds__(1024) void k_prep(const float* __restrict__ coarse,
                                               const int* __restrict__ rnd,
                                               const float* __restrict__ w1,
                                               const float* __restrict__ w2,
                                               float* __restrict__ mask_out) {
    extern __shared__ unsigned int dyn[];   // 32KB: okey[6144] then bitmap[8192]
    __shared__ int hist[256];
    __shared__ unsigned int selb[SELW];
    __shared__ unsigned int s_prefix;
    __shared__ int s_need;
    __shared__ int warp_tot[32];

    if (blockIdx.x >= PREP_SEL_BLOCKS) {
        // ---- weight repack: w1p[cb][o][q] = w1[o][cb*4+q] (zero pad) ----
        int t = (blockIdx.x - PREP_SEL_BLOCKS) * 1024 + threadIdx.x;
        if (t < W1P_ELEMS) {
            int cb = t >> 10;              // / (256*4)
            int rest = t & 1023;
            int o = rest >> 2, q = rest & 3;
            int c = cb * 4 + q;
            g_w1p[t] = (c < FEAT_DIM) ? w1[o*FEAT_DIM + c] : 0.f;
        } else {
            int t2 = t - W1P_ELEMS;
            if (t2 < W2P_ELEMS) {
                int cb = t2 >> 9;          // / (128*4)
                int rest = t2 & 511;
                int o = rest >> 2, q = rest & 3;
                int c = cb * 4 + q;
                g_w2p[t2] = (c < FEAT_DIM) ? w2[o*FEAT_DIM + c] : 0.f;
            }
        }
        return;
    }

    int b = blockIdx.x;
    int tid = threadIdx.x;

    // ---- 1. uncertainty -> monotone 32-bit okey (bit-identical to R2) ----
    for (int j = tid; j < NUM_OVER; j += 1024) {
        int idx = rnd[j];
        int h = idx / WW, w = idx % WW;
        float yc = (float)h * 0.25f - 0.375f;
        float xc = (float)w * 0.25f - 0.375f;
        int y0 = (int)floorf(yc); float fy = yc - (float)y0;
        int x0 = (int)floorf(xc); float fx = xc - (float)x0;
        int y0c = min(max(y0,   0), CHW-1), y1c = min(max(y0+1, 0), CHW-1);
        int x0c = min(max(x0,   0), CHW-1), x1c = min(max(x0+1, 0), CHW-1);
        float p[3];
        const float* base = coarse + (size_t)b * NCc * CHW * CHW;
#pragma unroll
        for (int c = 0; c < 3; c++) {
            const float* pc = base + c * CHW * CHW;
            float v00 = pc[y0c*CHW + x0c], v01 = pc[y0c*CHW + x1c];
            float v10 = pc[y1c*CHW + x0c], v11 = pc[y1c*CHW + x1c];
            float top = v00 * (1.f - fx) + v01 * fx;
            float bot = v10 * (1.f - fx) + v11 * fx;
            p[c] = top * (1.f - fy) + bot * fy;
        }
        float m  = fmaxf(p[0], fmaxf(p[1], p[2]));
        float e0 = expf(p[0]-m), e1 = expf(p[1]-m), e2 = expf(p[2]-m);
        float s  = e0 + e1 + e2;
        float q0 = e0/s, q1 = e1/s, q2 = e2/s;
        float mx  = fmaxf(q0, fmaxf(q1, q2));
        float mn  = fminf(q0, fminf(q1, q2));
        float mid = q0 + q1 + q2 - mx - mn;
        float u = 1.0f - (mx - mid);
        unsigned int bits = __float_as_uint(u);
        // larger okey == larger u (total order incl. negatives)
        dyn[j] = bits ^ ((bits >> 31) ? 0xFFFFFFFFu : 0x80000000u);
    }
    if (tid == 0) { s_prefix = 0u; s_need = STEP1; }
    __syncthreads();

    // ---- 2. radix threshold: find exact T = key of rank STEP1 ----
#pragma unroll
    for (int lvl = 0; lvl < 4; lvl++) {
        int shift = 24 - 8*lvl;
        unsigned int hi_mask = lvl ? (0xFFFFFFFFu << (shift + 8)) : 0u;
        for (int i = tid; i < 256; i += 1024) hist[i] = 0;
        __syncthreads();
        unsigned int pref = s_prefix;
        for (int j = tid; j < NUM_OVER; j += 1024) {
            unsigned int ok = dyn[j];
            if ((ok & hi_mask) == pref)
                atomicAdd(&hist[(ok >> shift) & 255], 1);
        }
        __syncthreads();
        if (tid == 0) {
            int acc = 0, bb = 255;
            for (; bb > 0; bb--) {
                if (acc + hist[bb] >= s_need) break;
                acc += hist[bb];
            }
            s_need -= acc;
            s_prefix |= (unsigned int)bb << shift;
        }
        __syncthreads();
    }
    unsigned int T = s_prefix;
    int need = s_need;                      // #elements equal to T to take

    // ---- 3. selection flags (ties: smallest candidate index first) ----
    for (int i = tid; i < SELW; i += 1024) selb[i] = 0u;
    __syncthreads();
    for (int j = tid; j < NUM_OVER; j += 1024) {
        unsigned int ok = dyn[j];
        bool sel = ok > T;
        if (ok == T) {
            int rank = 0;
            for (int k = 0; k < j; k++) rank += (dyn[k] == T);
            sel = rank < need;
        }
        if (sel) atomicOr(&selb[j >> 5], 1u << (j & 31));
    }
    __syncthreads();

    // ---- 4. bitmap of linear indices (reuse dyn) ----
    for (int w = tid; w < NWORDS; w += 1024) dyn[w] = 0u;
    __syncthreads();
    for (int j = tid; j < NUM_OVER; j += 1024)
        if ((selb[j >> 5] >> (j & 31)) & 1u) {
            int lin = rnd[j];
            atomicOr(&dyn[lin >> 5], 1u << (lin & 31));
        }
    for (int i = tid; i < STEP2; i += 1024) {
        int lin = rnd[HH*WW - STEP2 + i];
        atomicOr(&dyn[lin >> 5], 1u << (lin & 31));
    }
    __syncthreads();

    // ---- 5. popcount scan + ordered emit ----
    int w0 = tid * 8;
    unsigned int words[8];
    int cnt = 0;
#pragma unroll
    for (int q = 0; q < 8; q++) { words[q] = dyn[w0 + q]; cnt += __popc(words[q]); }
    int lane = tid & 31, wid = tid >> 5;
    int incl = cnt;
#pragma unroll
    for (int o = 1; o < 32; o <<= 1) {
        int v = __shfl_up_sync(0xFFFFFFFFu, incl, o);
        if (lane >= o) incl += v;
    }
    if (lane == 31) warp_tot[wid] = incl;
    __syncthreads();
    int base = 0;
    for (int ww = 0; ww < 32; ww++) if (ww < wid) base += warp_tot[ww];
    int offset = base + incl - cnt;         // exclusive prefix
#pragma unroll
    for (int q = 0; q < 8; q++) {
        unsigned int m = words[q];
        int linbase = (w0 + q) * 32;
        while (m) {
            int bpos = __ffs(m) - 1; m &= m - 1;
            int lin = linbase + bpos;
            g_pts[b*NPTS + offset] = lin;
            mask_out[b*HH*WW + lin] = 1.0f;
            offset++;
        }
    }
}

// =========================================================================
// k_sample: gather fine (256ch, x2 bilinear) + coarse logits per point.
// Warp-uniform float2 fast path when x-taps are an aligned adjacent pair.
// =========================================================================
__global__ void k_sample(const float* __restrict__ fine, const float* __restrict__ coarse) {
    __shared__ int   sy0, sy1, sx0, sx1, cy0, cy1, cx0, cx1, sfast;
    __shared__ float sfy, sfx, cfy, cfx;
    int g = blockIdx.x;               // b*2048 + n (sorted order)
    int b = g >> 11;
    if (threadIdx.x == 0) {
        int idx = g_pts[g];
        int h = idx / WW, w = idx % WW;
        // fine: 256 -> 512, src = i/2 - 0.25
        float yf = (float)h * 0.5f - 0.25f;
        float xf = (float)w * 0.5f - 0.25f;
        int y0 = (int)floorf(yf); sfy = yf - (float)y0;
        int x0 = (int)floorf(xf); sfx = xf - (float)x0;
        sy0 = min(max(y0,   0), FHW-1); sy1 = min(max(y0+1, 0), FHW-1);
        sx0 = min(max(x0,   0), FHW-1); sx1 = min(max(x0+1, 0), FHW-1);
        sfast = (sx1 == sx0 + 1) && ((sx0 & 1) == 0);
        // coarse: 128 -> 512, src = i/4 - 0.375
        float yc = (float)h * 0.25f - 0.375f;
        float xc = (float)w * 0.25f - 0.375f;
        int cy = (int)floorf(yc); cfy = yc - (float)cy;
        int cx = (int)floorf(xc); cfx = xc - (float)cx;
        cy0 = min(max(cy,   0), CHW-1); cy1 = min(max(cy+1, 0), CHW-1);
        cx0 = min(max(cx,   0), CHW-1); cx1 = min(max(cx+1, 0), CHW-1);
    }
    __syncthreads();
    int c = threadIdx.x;              // 256 channels
    {
        const float* pf = fine + ((size_t)b * CF + c) * (FHW * FHW);
        float v00, v01, v10, v11;
        if (sfast) {                  // warp-uniform branch
            float2 a = *(const float2*)(pf + sy0*FHW + sx0);
            float2 d = *(const float2*)(pf + sy1*FHW + sx0);
            v00 = a.x; v01 = a.y; v10 = d.x; v11 = d.y;
        } else {
            v00 = pf[sy0*FHW + sx0]; v01 = pf[sy0*FHW + sx1];
            v10 = pf[sy1*FHW + sx0]; v11 = pf[sy1*FHW + sx1];
        }
        float top = v00 * (1.f - sfx) + v01 * sfx;
        float bot = v10 * (1.f - sfx) + v11 * sfx;
        g_flat[(size_t)g * CF + c] = top * (1.f - sfy) + bot * sfy;
    }
    if (c < NCc) {
        const float* pc = coarse + ((size_t)b * NCc + c) * (CHW * CHW);
        float v00 = pc[cy0*CHW + cx0], v01 = pc[cy0*CHW + cx1];
        float v10 = pc[cy1*CHW + cx0], v11 = pc[cy1*CHW + cx1];
        float top = v00 * (1.f - cfx) + v01 * cfx;
        float bot = v10 * (1.f - cfx) + v11 * cfx;
        g_flat[FINE_FLAT + (size_t)g * NCc + c] = top * (1.f - cfy) + bot * cfy;
    }
}

// =========================================================================
// k_mlp: 16 rows/block, channel loop vectorized x4 (LDG.128 weights,
// LDS.128 broadcast features) -> FMA-pipe bound.
// Rows read the SCRAMBLED flat buffer at g*259 exactly like the reference
// reshape (fine.ravel() ++ coarse.ravel() -> (B, NPTS, 259)).
// =========================================================================
__global__ __launch_bounds__(256) void k_mlp(const float* __restrict__ w3,
                                             const float* __restrict__ pa,
                                             float* __restrict__ out) {
    __shared__ __align__(16) float xs[RPB][FEAT_PAD];
    __shared__ __align__(16) float l1s[RPB][FEAT_PAD];
    __shared__ __align__(16) float l2s[RPB][128];
    int g0 = blockIdx.x * RPB;
    float a = *pa;
    for (int t = threadIdx.x; t < RPB*FEAT_DIM; t += 256) {
        int r = t / FEAT_DIM, c = t % FEAT_DIM;
        float v = g_flat[(size_t)(g0 + r) * FEAT_DIM + c];
        xs[r][c] = v;
        if (c >= 256) l1s[r][c] = v;          // tail feeds layer 2 directly
    }
    if (threadIdx.x < RPB) {                  // pad column 259 with zeros
        xs[threadIdx.x][259] = 0.f;
        l1s[threadIdx.x][259] = 0.f;
    }
    __syncthreads();
    // ---- layer 1: 259 -> 256, prelu ----
    int o = threadIdx.x;
    float acc[RPB];
#pragma unroll
    for (int r = 0; r < RPB; r++) acc[r] = 0.f;
    const float4* w1p4 = (const float4*)g_w1p;
    for (int cb = 0; cb < NCB1; cb++) {
        float4 wv = w1p4[cb*256 + o];
#pragma unroll
        for (int r = 0; r < RPB; r++) {
            float4 x4 = *(const float4*)&xs[r][cb*4];
            acc[r] = fmaf(wv.x, x4.x, acc[r]);
            acc[r] = fmaf(wv.y, x4.y, acc[r]);
            acc[r] = fmaf(wv.z, x4.z, acc[r]);
            acc[r] = fmaf(wv.w, x4.w, acc[r]);
        }
    }
#pragma unroll
    for (int r = 0; r < RPB; r++) l1s[r][o] = acc[r] >= 0.f ? acc[r] : a * acc[r];
    __syncthreads();
    // ---- layer 2: [l1(256) ++ tail(3)] -> 128, prelu ----
    {
        int o2 = threadIdx.x & 127;
        int r0 = threadIdx.x >> 7;            // 0 or 1; rows r0, r0+2, ...
        float acc2[RPB/2];
#pragma unroll
        for (int rr = 0; rr < RPB/2; rr++) acc2[rr] = 0.f;
        const float4* w2p4 = (const float4*)g_w2p;
        for (int cb = 0; cb < NCB1; cb++) {
            float4 wv = w2p4[cb*128 + o2];
#pragma unroll
            for (int rr = 0; rr < RPB/2; rr++) {
                float4 x4 = *(const float4*)&l1s[r0 + 2*rr][cb*4];
                acc2[rr] = fmaf(wv.x, x4.x, acc2[rr]);
                acc2[rr] = fmaf(wv.y, x4.y, acc2[rr]);
                acc2[rr] = fmaf(wv.z, x4.z, acc2[rr]);
                acc2[rr] = fmaf(wv.w, x4.w, acc2[rr]);
            }
        }
#pragma unroll
        for (int rr = 0; rr < RPB/2; rr++) {
            float v = acc2[rr];
            l2s[r0 + 2*rr][o2] = v >= 0.f ? v : a * v;
        }
    }
    __syncthreads();
    // ---- layer 3: [l2(128) ++ tail(3)] -> 3 ----
    if (threadIdx.x < RPB*NCc) {
        int r = threadIdx.x / 3, oo = threadIdx.x % 3;
        float s = 0.f;
        for (int c = 0; c < 128; c++) s = fmaf(w3[oo*131 + c], l2s[r][c], s);
#pragma unroll
        for (int t = 0; t < 3; t++)  s = fmaf(w3[oo*131 + 128 + t], xs[r][256 + t], s);
        int g = g0 + r;
        int b = g >> 11, n = g & 2047;
        out[(b*NCc + oo)*NPTS + n] = s;
    }
}

// ---------------- launch ----------------
extern "C" void kernel_launch(void* const* d_in, const int* in_sizes, int n_in,
                              void* d_out, int out_size) {
    const float* fine   = (const float*)d_in[0];   // (2,256,256,256)
    const float* coarse = (const float*)d_in[1];   // (2,3,128,128)
    const float* w1     = (const float*)d_in[2];   // (256,259)
    const float* w2     = (const float*)d_in[3];   // (128,259)
    const float* w3     = (const float*)d_in[4];   // (3,131)
    const float* pa     = (const float*)d_in[5];   // scalar
    const int*   rnd    = (const int*)d_in[6];     // (262144,)
    float* out = (float*)d_out;

    cudaFuncSetAttribute(k_prep, cudaFuncAttributeMaxDynamicSharedMemorySize,
                         NWORDS * (int)sizeof(unsigned int));

    cudaMemsetAsync(out + OUT_OFF, 0, (size_t)MASK_SIZE * sizeof(float), 0);
    k_prep<<<PREP_SEL_BLOCKS + PREP_REPACK_BLOCKS, 1024,
             NWORDS * sizeof(unsigned int)>>>(coarse, rnd, w1, w2, out + OUT_OFF);
    k_sample<<<NROWS, 256>>>(fine, coarse);
    k_mlp<<<NROWS/RPB, 256>>>(w3, pa, out);
    (void)in_sizes; (void)n_in; (void)out_size;
}

// round 6
// speedup vs baseline: 1.9746x; 1.4423x over previous
#include <cuda_runtime.h>
#include <math.h>

#define HH 512
#define WW 512
#define CHW 128
#define FHW 256
#define CF 256
#define NCc 3
#define NPTS 2048
#define NUM_OVER 6144
#define CHUNK 6                              // NUM_OVER / 1024
#define STEP1 1536
#define STEP2 512
#define BB 2
#define FEAT_DIM 259
#define FEAT_PAD 260
#define NCB1 65                              // 260/4
#define NROWS (BB*NPTS)                      // 4096
#define FINE_FLAT (BB*NPTS*CF)               // 1048576
#define OUT_OFF (BB*NCc*NPTS)                // 12288
#define MASK_SIZE (BB*HH*WW)
#define RPB 16
#define NPAIR (RPB/2)                        // 8
#define NWORDS (HH*WW/32)                    // 8192 (32KB)
#define W1P_ELEMS (NCB1*256*4)
#define W2P_ELEMS (NCB1*128*4)
#define PREP_SEL_BLOCKS 2
#define PREP_REPACK_BLOCKS 98
#define P_MAX 18                             // fine points touched per MLP block

// ---------------- device scratch ----------------
__device__ int   g_pts[BB*NPTS];
__device__ float g_cflat[BB*NPTS*NCc];       // coarse logits at sorted points
__device__ float g_w1p[W1P_ELEMS];           // [cb][o][q]
__device__ float g_w2p[W2P_ELEMS];

// ---------------- f32x2 helpers (FFMA2 path, bit-identical lanewise fma) --
__device__ __forceinline__ unsigned long long pk2(float lo, float hi) {
    unsigned long long r;
    asm("mov.b64 %0, {%1,%2};" : "=l"(r) : "f"(lo), "f"(hi));
    return r;
}
__device__ __forceinline__ void upk2(unsigned long long v, float& lo, float& hi) {
    asm("mov.b64 {%0,%1}, %2;" : "=f"(lo), "=f"(hi) : "l"(v));
}
__device__ __forceinline__ void fma2(unsigned long long& d, unsigned long long a,
                                     unsigned long long b) {
    asm("fma.rn.f32x2 %0, %1, %2, %0;" : "+l"(d) : "l"(a), "l"(b));
}

// =========================================================================
// k_prep: blocks 0..1 -> per-batch selection (radix threshold, all-parallel)
//                        + ordered emit + mask + coarse-logit gather
//         blocks 2..  -> weight repack
// =========================================================================
__global__ __launch_bounds__(1024) void k_prep(const float* __restrict__ coarse,
                                               const int* __restrict__ rnd,
                                               const float* __restrict__ w1,
                                               const float* __restrict__ w2,
                                               float* __restrict__ mask_out) {
    extern __shared__ unsigned int dyn[];    // 32KB: okey[6144] -> bitmap[8192]
    __shared__ int hist[256];
    __shared__ int sfxsum[257];
    __shared__ int warp_tot[32];
    __shared__ unsigned int s_prefix;
    __shared__ int s_need;

    if (blockIdx.x >= PREP_SEL_BLOCKS) {
        int t = (blockIdx.x - PREP_SEL_BLOCKS) * 1024 + threadIdx.x;
        if (t < W1P_ELEMS) {
            int cb = t >> 10, rest = t & 1023;
            int o = rest >> 2, q = rest & 3, c = cb * 4 + q;
            g_w1p[t] = (c < FEAT_DIM) ? w1[o*FEAT_DIM + c] : 0.f;
        } else {
            int t2 = t - W1P_ELEMS;
            if (t2 < W2P_ELEMS) {
                int cb = t2 >> 9, rest = t2 & 511;
                int o = rest >> 2, q = rest & 3, c = cb * 4 + q;
                g_w2p[t2] = (c < FEAT_DIM) ? w2[o*FEAT_DIM + c] : 0.f;
            }
        }
        return;
    }

    int b = blockIdx.x;
    int tid = threadIdx.x;
    int lane = tid & 31, wrp = tid >> 5;

    // ---- 1. uncertainty -> monotone okey (chunked: thread owns j=tid*6+jj)
    for (int jj = 0; jj < CHUNK; jj++) {
        int j = tid * CHUNK + jj;
        int idx = rnd[j];
        int h = idx / WW, w = idx % WW;
        float yc = (float)h * 0.25f - 0.375f;
        float xc = (float)w * 0.25f - 0.375f;
        int y0 = (int)floorf(yc); float fy = yc - (float)y0;
        int x0 = (int)floorf(xc); float fx = xc - (float)x0;
        int y0c = min(max(y0,   0), CHW-1), y1c = min(max(y0+1, 0), CHW-1);
        int x0c = min(max(x0,   0), CHW-1), x1c = min(max(x0+1, 0), CHW-1);
        float p[3];
        const float* base = coarse + (size_t)b * NCc * CHW * CHW;
#pragma unroll
        for (int c = 0; c < 3; c++) {
            const float* pc = base + c * CHW * CHW;
            float v00 = pc[y0c*CHW + x0c], v01 = pc[y0c*CHW + x1c];
            float v10 = pc[y1c*CHW + x0c], v11 = pc[y1c*CHW + x1c];
            float top = v00 * (1.f - fx) + v01 * fx;
            float bot = v10 * (1.f - fx) + v11 * fx;
            p[c] = top * (1.f - fy) + bot * fy;
        }
        float m  = fmaxf(p[0], fmaxf(p[1], p[2]));
        float e0 = expf(p[0]-m), e1 = expf(p[1]-m), e2 = expf(p[2]-m);
        float s  = e0 + e1 + e2;
        float q0 = e0/s, q1 = e1/s, q2 = e2/s;
        float mx  = fmaxf(q0, fmaxf(q1, q2));
        float mn  = fminf(q0, fminf(q1, q2));
        float mid = q0 + q1 + q2 - mx - mn;
        float u = 1.0f - (mx - mid);
        unsigned int bits = __float_as_uint(u);
        dyn[j] = bits ^ ((bits >> 31) ? 0xFFFFFFFFu : 0x80000000u);
    }
    if (tid == 0) { s_prefix = 0u; s_need = STEP1; }
    __syncthreads();

    // ---- 2. radix threshold, parallel suffix scan per level ----
    for (int lvl = 0; lvl < 4; lvl++) {
        int shift = 24 - 8*lvl;
        unsigned int hi_mask = lvl ? (0xFFFFFFFFu << (shift + 8)) : 0u;
        unsigned int pref = s_prefix;
        int need = s_need;
        if (tid < 256) hist[tid] = 0;
        __syncthreads();
#pragma unroll
        for (int jj = 0; jj < CHUNK; jj++) {
            unsigned int ok = dyn[tid*CHUNK + jj];
            if ((ok & hi_mask) == pref) atomicAdd(&hist[(ok >> shift) & 255], 1);
        }
        __syncthreads();
        // suffix sums: thread tid (<256) accumulates buckets 255..255-tid
        int x = (tid < 256) ? hist[255 - tid] : 0;
#pragma unroll
        for (int o = 1; o < 32; o <<= 1) {
            int y = __shfl_up_sync(0xFFFFFFFFu, x, o);
            if (lane >= o) x += y;
        }
        if (tid < 256 && lane == 31) warp_tot[wrp] = x;
        __syncthreads();
        if (tid < 256) {
            int basew = 0;
            for (int wq = 0; wq < wrp; wq++) basew += warp_tot[wq];
            sfxsum[255 - tid] = x + basew;
        }
        __syncthreads();
        if (tid < 256) {
            int S  = sfxsum[tid];
            int S1 = (tid == 255) ? 0 : sfxsum[tid + 1];
            if (S >= need && S1 < need) {       // exactly one thread
                s_prefix = pref | ((unsigned int)tid << shift);
                s_need = need - S1;
            }
        }
        __syncthreads();
    }
    unsigned int T = s_prefix;
    int need = s_need;

    // ---- 3. tie ranks via block scan (index order == chunk order) ----
    unsigned int okv[CHUNK];
    int localeq = 0;
#pragma unroll
    for (int jj = 0; jj < CHUNK; jj++) {
        okv[jj] = dyn[tid*CHUNK + jj];
        localeq += (okv[jj] == T);
    }
    {
        int x = localeq;
#pragma unroll
        for (int o = 1; o < 32; o <<= 1) {
            int y = __shfl_up_sync(0xFFFFFFFFu, x, o);
            if (lane >= o) x += y;
        }
        if (lane == 31) warp_tot[wrp] = x;
        __syncthreads();
        int basew = 0;
        for (int wq = 0; wq < wrp; wq++) basew += warp_tot[wq];
        int rank = basew + x - localeq;          // exclusive among ties
        unsigned int selmask = 0;
#pragma unroll
        for (int jj = 0; jj < CHUNK; jj++) {
            bool sel = okv[jj] > T;
            if (okv[jj] == T) { sel = (rank < need); rank++; }
            if (sel) selmask |= 1u << jj;
        }
        __syncthreads();                         // done reading dyn as keys
        // ---- 4. bitmap of linear indices (reuse dyn) ----
        for (int w = tid; w < NWORDS; w += 1024) dyn[w] = 0u;
        __syncthreads();
#pragma unroll
        for (int jj = 0; jj < CHUNK; jj++)
            if ((selmask >> jj) & 1u) {
                int lin = rnd[tid*CHUNK + jj];
                atomicOr(&dyn[lin >> 5], 1u << (lin & 31));
            }
    }
    for (int i = tid; i < STEP2; i += 1024) {
        int lin = rnd[HH*WW - STEP2 + i];
        atomicOr(&dyn[lin >> 5], 1u << (lin & 31));
    }
    __syncthreads();

    // ---- 5. popcount scan + ordered emit ----
    {
        int w0 = tid * 8;
        unsigned int words[8];
        int cnt = 0;
#pragma unroll
        for (int q = 0; q < 8; q++) { words[q] = dyn[w0 + q]; cnt += __popc(words[q]); }
        int incl = cnt;
#pragma unroll
        for (int o = 1; o < 32; o <<= 1) {
            int v = __shfl_up_sync(0xFFFFFFFFu, incl, o);
            if (lane >= o) incl += v;
        }
        if (lane == 31) warp_tot[wrp] = incl;
        __syncthreads();
        int basew = 0;
        for (int wq = 0; wq < wrp; wq++) basew += warp_tot[wq];
        int offset = basew + incl - cnt;
#pragma unroll
        for (int q = 0; q < 8; q++) {
            unsigned int m = words[q];
            int linbase = (w0 + q) * 32;
            while (m) {
                int bpos = __ffs(m) - 1; m &= m - 1;
                int lin = linbase + bpos;
                g_pts[b*NPTS + offset] = lin;
                mask_out[b*HH*WW + lin] = 1.0f;
                offset++;
            }
        }
    }
    __syncthreads();                             // g_pts visible block-wide

    // ---- 6. coarse logits at the sorted points (feeds MLP tail/concat) ----
    for (int t = tid; t < NPTS; t += 1024) {
        int lin = g_pts[b*NPTS + t];
        int h = lin >> 9, w = lin & 511;
        float yc = (float)h * 0.25f - 0.375f;
        float xc = (float)w * 0.25f - 0.375f;
        int cy = (int)floorf(yc); float cfy = yc - (float)cy;
        int cx = (int)floorf(xc); float cfx = xc - (float)cx;
        int cy0 = min(max(cy,   0), CHW-1), cy1 = min(max(cy+1, 0), CHW-1);
        int cx0 = min(max(cx,   0), CHW-1), cx1 = min(max(cx+1, 0), CHW-1);
#pragma unroll
        for (int c = 0; c < 3; c++) {
            const float* pc = coarse + ((size_t)b * NCc + c) * (CHW * CHW);
            float v00 = pc[cy0*CHW + cx0], v01 = pc[cy0*CHW + cx1];
            float v10 = pc[cy1*CHW + cx0], v11 = pc[cy1*CHW + cx1];
            float top = v00 * (1.f - cfx) + v01 * cfx;
            float bot = v10 * (1.f - cfx) + v11 * cfx;
            g_cflat[(b*NPTS + t)*NCc + c] = top * (1.f - cfy) + bot * cfy;
        }
    }
}

// =========================================================================
// k_smlp: fused fine-gather + 3-layer MLP, 16 rows/block, FFMA2 math.
// Row g reads SCRAMBLED flat index f = g*259+c: f<FINE_FLAT -> fine feature
// of point f>>8 channel f&255 (gathered here); else g_cflat[f-FINE_FLAT].
// =========================================================================
__global__ __launch_bounds__(256) void k_smlp(const float* __restrict__ fine,
                                              const float* __restrict__ w3,
                                              const float* __restrict__ pa,
                                              float* __restrict__ out) {
    extern __shared__ float sm[];
    float* fseg = sm;                                  // P_MAX*256
    float* xsp  = fseg + P_MAX*256;                    // 8 pairs x 260 ch x2
    float* l1p  = xsp  + NPAIR*FEAT_PAD*2;             // 8 pairs x 260 ch x2
    float* l2s  = l1p  + NPAIR*FEAT_PAD*2;             // 16 x 128
    __shared__ int   c_b[P_MAX], c_y0[P_MAX], c_y1[P_MAX],
                     c_x0[P_MAX], c_x1[P_MAX], c_fast[P_MAX];
    __shared__ float c_fy[P_MAX], c_fx[P_MAX];

    int tid = threadIdx.x;
    int g0 = blockIdx.x * RPB;
    float a = *pa;

    int f0 = g0 * FEAT_DIM;
    int f1 = (g0 + RPB) * FEAT_DIM - 1;
    int p_lo = 0, np = 0;
    if (f0 < FINE_FLAT) {
        p_lo = f0 >> 8;
        np = (min(f1, FINE_FLAT - 1) >> 8) - p_lo + 1;
    }
    int p_base = p_lo << 8;

    // ---- point coords (fine bilinear: 256->512, src = i/2 - 0.25) ----
    if (tid < np) {
        int p = p_lo + tid;
        int idx = g_pts[p];
        int h = idx >> 9, w = idx & 511;
        float yf = (float)h * 0.5f - 0.25f;
        float xf = (float)w * 0.5f - 0.25f;
        int y0 = (int)floorf(yf); c_fy[tid] = yf - (float)y0;
        int x0 = (int)floorf(xf); c_fx[tid] = xf - (float)x0;
        int sy0 = min(max(y0,   0), FHW-1), sy1 = min(max(y0+1, 0), FHW-1);
        int sx0 = min(max(x0,   0), FHW-1), sx1 = min(max(x0+1, 0), FHW-1);
        c_y0[tid] = sy0; c_y1[tid] = sy1; c_x0[tid] = sx0; c_x1[tid] = sx1;
        c_fast[tid] = (sx1 == sx0 + 1) && ((sx0 & 1) == 0);
        c_b[tid] = p >> 11;
    }
    __syncthreads();

    // ---- gather fine channels for the window's points ----
    for (int i = 0; i < np; i++) {
        const float* pf = fine + ((size_t)c_b[i] * CF + tid) * (FHW * FHW);
        float v00, v01, v10, v11;
        float sfx = c_fx[i], sfy = c_fy[i];
        if (c_fast[i]) {                       // block-uniform branch
            float2 aa = *(const float2*)(pf + c_y0[i]*FHW + c_x0[i]);
            float2 dd = *(const float2*)(pf + c_y1[i]*FHW + c_x0[i]);
            v00 = aa.x; v01 = aa.y; v10 = dd.x; v11 = dd.y;
        } else {
            v00 = pf[c_y0[i]*FHW + c_x0[i]]; v01 = pf[c_y0[i]*FHW + c_x1[i]];
            v10 = pf[c_y1[i]*FHW + c_x0[i]]; v11 = pf[c_y1[i]*FHW + c_x1[i]];
        }
        float top = v00 * (1.f - sfx) + v01 * sfx;
        float bot = v10 * (1.f - sfx) + v11 * sfx;
        fseg[i*256 + tid] = top * (1.f - sfy) + bot * sfy;
    }
    __syncthreads();

    // ---- build row-pair features xsp[pr][c] = (row 2pr, row 2pr+1) ----
    for (int t = tid; t < RPB*FEAT_PAD; t += 256) {
        int r = t & 15, c = t >> 4;
        float v = 0.f;
        if (c < FEAT_DIM) {
            int f = (g0 + r) * FEAT_DIM + c;
            v = (f < FINE_FLAT) ? fseg[f - p_base] : g_cflat[f - FINE_FLAT];
        }
        int pi = ((r >> 1) * FEAT_PAD + c) * 2 + (r & 1);
        xsp[pi] = v;
        if (c >= 256) l1p[pi] = v;             // tail feeds layer 2 (c=259 -> 0)
    }
    __syncthreads();

    // ---- layer 1: 259 -> 256, prelu (FFMA2 over row pairs) ----
    {
        int o = tid;
        unsigned long long accp[NPAIR];
#pragma unroll
        for (int pr = 0; pr < NPAIR; pr++) accp[pr] = 0ull;
        const float4* w1p4 = (const float4*)g_w1p;
        for (int cb = 0; cb < NCB1; cb++) {
            float4 wv = w1p4[cb*256 + o];
            unsigned long long wp0 = pk2(wv.x, wv.x), wp1 = pk2(wv.y, wv.y);
            unsigned long long wp2 = pk2(wv.z, wv.z), wp3 = pk2(wv.w, wv.w);
#pragma unroll
            for (int pr = 0; pr < NPAIR; pr++) {
                const ulonglong2* xp =
                    (const ulonglong2*)&xsp[(pr*FEAT_PAD + cb*4) * 2];
                ulonglong2 u0 = xp[0], u1 = xp[1];
                fma2(accp[pr], wp0, u0.x);
                fma2(accp[pr], wp1, u0.y);
                fma2(accp[pr], wp2, u1.x);
                fma2(accp[pr], wp3, u1.y);
            }
        }
#pragma unroll
        for (int pr = 0; pr < NPAIR; pr++) {
            float lo, hi; upk2(accp[pr], lo, hi);
            lo = lo >= 0.f ? lo : a * lo;
            hi = hi >= 0.f ? hi : a * hi;
            ((float2*)l1p)[pr*FEAT_PAD + o] = make_float2(lo, hi);
        }
    }
    __syncthreads();

    // ---- layer 2: 259 -> 128, prelu ----
    {
        int o2 = tid & 127;
        int rh = tid >> 7;                     // half: pairs rh*4 .. rh*4+3
        unsigned long long acc2[4];
#pragma unroll
        for (int pp = 0; pp < 4; pp++) acc2[pp] = 0ull;
        const float4* w2p4 = (const float4*)g_w2p;
        for (int cb = 0; cb < NCB1; cb++) {
            float4 wv = w2p4[cb*128 + o2];
            unsigned long long wp0 = pk2(wv.x, wv.x), wp1 = pk2(wv.y, wv.y);
            unsigned long long wp2 = pk2(wv.z, wv.z), wp3 = pk2(wv.w, wv.w);
#pragma unroll
            for (int pp = 0; pp < 4; pp++) {
                int pr = rh*4 + pp;
                const ulonglong2* xp =
                    (const ulonglong2*)&l1p[(pr*FEAT_PAD + cb*4) * 2];
                ulonglong2 u0 = xp[0], u1 = xp[1];
                fma2(acc2[pp], wp0, u0.x);
                fma2(acc2[pp], wp1, u0.y);
                fma2(acc2[pp], wp2, u1.x);
                fma2(acc2[pp], wp3, u1.y);
            }
        }
#pragma unroll
        for (int pp = 0; pp < 4; pp++) {
            int pr = rh*4 + pp;
            float lo, hi; upk2(acc2[pp], lo, hi);
            lo = lo >= 0.f ? lo : a * lo;
            hi = hi >= 0.f ? hi : a * hi;
            l2s[(2*pr  )*128 + o2] = lo;
            l2s[(2*pr+1)*128 + o2] = hi;
        }
    }
    __syncthreads();

    // ---- layer 3: 131 -> 3 ----
    if (tid < RPB*NCc) {
        int r = tid / 3, oo = tid % 3;
        float s = 0.f;
        for (int c = 0; c < 128; c++) s = fmaf(w3[oo*131 + c], l2s[r*128 + c], s);
#pragma unroll
        for (int t = 0; t < 3; t++) {
            float xt = xsp[((r >> 1)*FEAT_PAD + 256 + t)*2 + (r & 1)];
            s = fmaf(w3[oo*131 + 128 + t], xt, s);
        }
        int g = g0 + r;
        int b = g >> 11, n = g & 2047;
        out[(b*NCc + oo)*NPTS + n] = s;
    }
}

// ---------------- launch ----------------
extern "C" void kernel_launch(void* const* d_in, const int* in_sizes, int n_in,
                              void* d_out, int out_size) {
    const float* fine   = (const float*)d_in[0];
    const float* coarse = (const float*)d_in[1];
    const float* w1     = (const float*)d_in[2];
    const float* w2     = (const float*)d_in[3];
    const float* w3     = (const float*)d_in[4];
    const float* pa     = (const float*)d_in[5];
    const int*   rnd    = (const int*)d_in[6];
    float* out = (float*)d_out;

    static int configured = 0;
    int smlp_smem = (P_MAX*256 + 2*NPAIR*FEAT_PAD*2 + RPB*128) * (int)sizeof(float);
    if (!configured) {
        cudaFuncSetAttribute(k_prep, cudaFuncAttributeMaxDynamicSharedMemorySize,
                             NWORDS * (int)sizeof(unsigned int));
        cudaFuncSetAttribute(k_smlp, cudaFuncAttributeMaxDynamicSharedMemorySize,
                             smlp_smem);
        configured = 1;
    }

    cudaMemsetAsync(out + OUT_OFF, 0, (size_t)MASK_SIZE * sizeof(float), 0);
    k_prep<<<PREP_SEL_BLOCKS + PREP_REPACK_BLOCKS, 1024,
             NWORDS * sizeof(unsigned int)>>>(coarse, rnd, w1, w2, out + OUT_OFF);
    k_smlp<<<NROWS/RPB, 256, smlp_smem>>>(fine, w3, pa, out);
    (void)in_sizes; (void)n_in; (void)out_size;
}